// round 1
// baseline (speedup 1.0000x reference)
#include <cuda_runtime.h>
#include <math.h>
#include <stdint.h>

// Problem constants (fixed by the reference)
#define BB 16
#define HH 32
#define DD 128
#define GG 8
#define SS 8192
#define KVG 4        // HH / GG : queries per kv group
#define NSPLIT 32    // splits per (b,g)
#define SPLIT_LEN 256 // SS / NSPLIT
#define WPB 8        // warps per block in partial kernel

// Scratch: per (b,g,split,q): acc[D] and (m,l)
__device__ float  g_acc[(size_t)BB * GG * NSPLIT * KVG * DD]; // 8 MB
__device__ float2 g_ml[(size_t)BB * GG * NSPLIT * KVG];

__device__ __forceinline__ float ex2f(float x) {
    float y;
    asm("ex2.approx.ftz.f32 %0, %1;" : "=f"(y) : "f"(x));
    return y;
}

__global__ void __launch_bounds__(256)
attn_partial(const float* __restrict__ Q,
             const float* __restrict__ K,
             const float* __restrict__ V,
             const int*   __restrict__ cache_seqlen)
{
    const int b    = blockIdx.z;
    const int g    = blockIdx.y;
    const int warp = threadIdx.x >> 5;
    const int lane = threadIdx.x & 31;
    const int split = blockIdx.x * WPB + warp;

    const int len  = cache_seqlen[b];
    const int s0   = split * SPLIT_LEN;
    const int send = min(s0 + SPLIT_LEN, len);
    const int n    = send - s0;   // may be <= 0

    // Load Q for the 4 queries of this group; fold softmax scale * log2(e)
    const float scale = 0.08838834764831845f * 1.4426950408889634f; // 1/sqrt(128) * log2(e)
    float4 qv[KVG];
#pragma unroll
    for (int q = 0; q < KVG; q++) {
        const float4* qp = (const float4*)(Q + ((size_t)(b * HH + g * KVG + q)) * DD);
        float4 t = qp[lane];
        qv[q] = make_float4(t.x * scale, t.y * scale, t.z * scale, t.w * scale);
    }

    float  m[KVG], l[KVG];
    float4 acc[KVG];
#pragma unroll
    for (int q = 0; q < KVG; q++) {
        m[q] = -INFINITY;
        l[q] = 0.f;
        acc[q] = make_float4(0.f, 0.f, 0.f, 0.f);
    }

    // K[b,s,g,d]: token stride = GG*DD floats = 256 float4
    const int strideF4 = (GG * DD) / 4;
    const float4* kp = (const float4*)(K + (((size_t)b * SS + s0) * GG + g) * DD) + lane;
    const float4* vp = (const float4*)(V + (((size_t)b * SS + s0) * GG + g) * DD) + lane;

    // per-token processing lambda-ish via macro to keep registers tight
#define PROCESS(kk, vv)                                                        \
    {                                                                          \
        float sc[KVG];                                                         \
        _Pragma("unroll")                                                      \
        for (int q = 0; q < KVG; q++)                                          \
            sc[q] = qv[q].x * kk.x + qv[q].y * kk.y +                          \
                    qv[q].z * kk.z + qv[q].w * kk.w;                           \
        _Pragma("unroll")                                                      \
        for (int off = 16; off; off >>= 1) {                                   \
            _Pragma("unroll")                                                  \
            for (int q = 0; q < KVG; q++)                                      \
                sc[q] += __shfl_xor_sync(0xffffffffu, sc[q], off);             \
        }                                                                      \
        _Pragma("unroll")                                                      \
        for (int q = 0; q < KVG; q++) {                                        \
            if (sc[q] <= m[q]) { /* warp-uniform branch */                     \
                float p = ex2f(sc[q] - m[q]);                                  \
                l[q] += p;                                                     \
                acc[q].x += p * vv.x; acc[q].y += p * vv.y;                    \
                acc[q].z += p * vv.z; acc[q].w += p * vv.w;                    \
            } else {                                                           \
                float alpha = ex2f(m[q] - sc[q]);                              \
                m[q] = sc[q];                                                  \
                l[q] = l[q] * alpha + 1.f;                                     \
                acc[q].x = acc[q].x * alpha + vv.x;                            \
                acc[q].y = acc[q].y * alpha + vv.y;                            \
                acc[q].z = acc[q].z * alpha + vv.z;                            \
                acc[q].w = acc[q].w * alpha + vv.w;                            \
            }                                                                  \
        }                                                                      \
    }

    int i = 0;
    for (; i + 4 <= n; i += 4) {
        float4 k0 = kp[0];
        float4 k1 = kp[strideF4];
        float4 k2 = kp[2 * strideF4];
        float4 k3 = kp[3 * strideF4];
        float4 v0 = vp[0];
        float4 v1 = vp[strideF4];
        float4 v2 = vp[2 * strideF4];
        float4 v3 = vp[3 * strideF4];
        kp += 4 * strideF4;
        vp += 4 * strideF4;
        PROCESS(k0, v0);
        PROCESS(k1, v1);
        PROCESS(k2, v2);
        PROCESS(k3, v3);
    }
    for (; i < n; i++) {
        float4 kk = kp[0];
        float4 vv = vp[0];
        kp += strideF4;
        vp += strideF4;
        PROCESS(kk, vv);
    }
#undef PROCESS

    // write partial (always, even if n<=0: m=-inf, l=0, acc=0 => zero weight)
    const size_t sg = ((size_t)(b * GG + g)) * NSPLIT + split;
#pragma unroll
    for (int q = 0; q < KVG; q++) {
        float4* ap = (float4*)(g_acc + (sg * KVG + q) * DD) + lane;
        *ap = acc[q];
        if (lane == 0) g_ml[sg * KVG + q] = make_float2(m[q], l[q]);
    }
}

__global__ void __launch_bounds__(128)
attn_combine(float* __restrict__ out)
{
    const int h = blockIdx.x;   // 0..HH-1
    const int b = blockIdx.y;   // 0..BB-1
    const int g = h / KVG;
    const int q = h % KVG;
    const int d = threadIdx.x;  // 0..127

    // index of split i into g_ml / row base of g_acc: base + i*KVG
    const size_t base = ((size_t)(b * GG + g)) * NSPLIT * KVG + q;

    __shared__ float2 s_ml[NSPLIT];
    if (threadIdx.x < NSPLIT)
        s_ml[threadIdx.x] = g_ml[base + (size_t)threadIdx.x * KVG];
    __syncthreads();

    float M = -INFINITY;
#pragma unroll
    for (int i = 0; i < NSPLIT; i++) M = fmaxf(M, s_ml[i].x);

    float num = 0.f, den = 0.f;
#pragma unroll 4
    for (int i = 0; i < NSPLIT; i++) {
        float2 ml = s_ml[i];
        float w = ex2f(ml.x - M);      // 0 for empty splits (m=-inf)
        den += w * ml.y;
        num += w * g_acc[(base + (size_t)i * KVG) * DD + d];
    }

    out[((size_t)b * HH + h) * DD + d] = num / den;
}

extern "C" void kernel_launch(void* const* d_in, const int* in_sizes, int n_in,
                              void* d_out, int out_size)
{
    const float* Q  = (const float*)d_in[0];
    const float* K  = (const float*)d_in[1];
    const float* V  = (const float*)d_in[2];
    const int* csl  = (const int*)d_in[3];
    float* out      = (float*)d_out;

    dim3 grid1(NSPLIT / WPB, GG, BB);   // 4 x 8 x 16 = 512 blocks
    attn_partial<<<grid1, 256>>>(Q, K, V, csl);

    dim3 grid2(HH, BB);                 // 32 x 16 = 512 blocks
    attn_combine<<<grid2, 128>>>(out);
}

// round 3
// speedup vs baseline: 1.5305x; 1.5305x over previous
#include <cuda_runtime.h>
#include <math.h>
#include <stdint.h>

// Problem constants (fixed by the reference)
#define BB 16
#define HH 32
#define DD 128
#define GG 8
#define SS 8192
#define KVG 4         // HH / GG : queries per kv group
#define NSPLIT 64     // splits per (b,g)
#define SPLIT_LEN 128 // SS / NSPLIT
#define WPB 8         // warps per block in partial kernel
#define NEG_BIG (-1.0e30f)

// Scratch: per (b,g,split,q): acc[D] and (m,l)
__device__ float  g_acc[(size_t)BB * GG * NSPLIT * KVG * DD]; // 16 MB
__device__ float2 g_ml[(size_t)BB * GG * NSPLIT * KVG];

__device__ __forceinline__ float ex2f(float x) {
    float y;
    asm("ex2.approx.ftz.f32 %0, %1;" : "=f"(y) : "f"(x));
    return y;
}

__global__ void __launch_bounds__(256, 2)
attn_partial(const float* __restrict__ Q,
             const float* __restrict__ K,
             const float* __restrict__ V,
             const int*   __restrict__ cache_seqlen)
{
    const int b    = blockIdx.z;
    const int g    = blockIdx.y;
    const int warp = threadIdx.x >> 5;
    const int lane = threadIdx.x & 31;
    const int split = blockIdx.x * WPB + warp;

    const int len  = cache_seqlen[b];
    const int s0   = split * SPLIT_LEN;
    const int n    = min(s0 + SPLIT_LEN, len) - s0;   // may be <= 0

    // Q for the 4 queries of this group; fold softmax scale * log2(e)
    const float scale = 0.08838834764831845f * 1.4426950408889634f;
    float4 qv[KVG];
#pragma unroll
    for (int q = 0; q < KVG; q++) {
        const float4* qp = (const float4*)(Q + ((size_t)(b * HH + g * KVG + q)) * DD);
        float4 t = qp[lane];
        qv[q] = make_float4(t.x * scale, t.y * scale, t.z * scale, t.w * scale);
    }

    float  m[KVG], l[KVG];
    float4 acc[KVG];
#pragma unroll
    for (int q = 0; q < KVG; q++) {
        m[q] = NEG_BIG;
        l[q] = 0.f;
        acc[q] = make_float4(0.f, 0.f, 0.f, 0.f);
    }

    const int strideF4 = (GG * DD) / 4;   // float4 stride between tokens = 256
    const float4* kp = (const float4*)(K + (((size_t)b * SS + s0) * GG + g) * DD) + lane;
    const float4* vp = (const float4*)(V + (((size_t)b * SS + s0) * GG + g) * DD) + lane;

    // Branchless, batch-of-4 online softmax.
    for (int i = 0; i < n; i += 4) {
        const int rem = n - i;   // >= 1 here

        // 8 independent LDG.128 in flight (loads never leave the split => always in-bounds)
        float4 kb[4], vb[4];
#pragma unroll
        for (int t = 0; t < 4; t++) kb[t] = kp[t * strideF4];
#pragma unroll
        for (int t = 0; t < 4; t++) vb[t] = vp[t * strideF4];
        kp += 4 * strideF4;
        vp += 4 * strideF4;

        // partial dot products: sc[t][q]
        float sc[4][KVG];
#pragma unroll
        for (int t = 0; t < 4; t++)
#pragma unroll
            for (int q = 0; q < KVG; q++)
                sc[t][q] = qv[q].x * kb[t].x + qv[q].y * kb[t].y +
                           qv[q].z * kb[t].z + qv[q].w * kb[t].w;

        // butterfly reduce all 16 values (fully independent -> deep ILP)
#pragma unroll
        for (int off = 16; off; off >>= 1)
#pragma unroll
            for (int t = 0; t < 4; t++)
#pragma unroll
                for (int q = 0; q < KVG; q++)
                    sc[t][q] += __shfl_xor_sync(0xffffffffu, sc[t][q], off);

        // mask tokens past the valid length (warp-uniform predicated selects)
#pragma unroll
        for (int t = 1; t < 4; t++)
            if (t >= rem)
#pragma unroll
                for (int q = 0; q < KVG; q++)
                    sc[t][q] = NEG_BIG;

        // one rescale per q per batch; no branches
#pragma unroll
        for (int q = 0; q < KVG; q++) {
            float mb = fmaxf(fmaxf(sc[0][q], sc[1][q]), fmaxf(sc[2][q], sc[3][q]));
            float mn = fmaxf(m[q], mb);
            float alpha = ex2f(m[q] - mn);
            m[q] = mn;
            float p0 = ex2f(sc[0][q] - mn);
            float p1 = ex2f(sc[1][q] - mn);
            float p2 = ex2f(sc[2][q] - mn);
            float p3 = ex2f(sc[3][q] - mn);
            l[q] = l[q] * alpha + ((p0 + p1) + (p2 + p3));
            float ax = acc[q].x * alpha, ay = acc[q].y * alpha,
                  az = acc[q].z * alpha, aw = acc[q].w * alpha;
            ax += p0 * vb[0].x; ay += p0 * vb[0].y; az += p0 * vb[0].z; aw += p0 * vb[0].w;
            ax += p1 * vb[1].x; ay += p1 * vb[1].y; az += p1 * vb[1].z; aw += p1 * vb[1].w;
            ax += p2 * vb[2].x; ay += p2 * vb[2].y; az += p2 * vb[2].z; aw += p2 * vb[2].w;
            ax += p3 * vb[3].x; ay += p3 * vb[3].y; az += p3 * vb[3].z; aw += p3 * vb[3].w;
            acc[q] = make_float4(ax, ay, az, aw);
        }
    }

    // write partial (always; empty split => m=NEG_BIG, l=0, acc=0 => zero weight)
    const size_t sg = ((size_t)(b * GG + g)) * NSPLIT + split;
#pragma unroll
    for (int q = 0; q < KVG; q++) {
        float4* ap = (float4*)(g_acc + (sg * KVG + q) * DD) + lane;
        *ap = acc[q];
        if (lane == 0) g_ml[sg * KVG + q] = make_float2(m[q], l[q]);
    }
}

__global__ void __launch_bounds__(128)
attn_combine(float* __restrict__ out)
{
    const int h = blockIdx.x;   // 0..HH-1
    const int b = blockIdx.y;   // 0..BB-1
    const int g = h / KVG;
    const int q = h % KVG;
    const int d = threadIdx.x;  // 0..127

    const size_t base = ((size_t)(b * GG + g)) * NSPLIT * KVG + q;

    __shared__ float2 s_ml[NSPLIT];
    if (threadIdx.x < NSPLIT)
        s_ml[threadIdx.x] = g_ml[base + (size_t)threadIdx.x * KVG];
    __syncthreads();

    float M = NEG_BIG;
#pragma unroll
    for (int i = 0; i < NSPLIT; i++) M = fmaxf(M, s_ml[i].x);

    float num = 0.f, den = 0.f;
#pragma unroll 8
    for (int i = 0; i < NSPLIT; i++) {
        float2 ml = s_ml[i];
        float w = ex2f(ml.x - M);      // 0 for empty splits
        den += w * ml.y;
        num += w * g_acc[(base + (size_t)i * KVG) * DD + d];
    }

    out[((size_t)b * HH + h) * DD + d] = num / den;
}

extern "C" void kernel_launch(void* const* d_in, const int* in_sizes, int n_in,
                              void* d_out, int out_size)
{
    const float* Q  = (const float*)d_in[0];
    const float* K  = (const float*)d_in[1];
    const float* V  = (const float*)d_in[2];
    const int* csl  = (const int*)d_in[3];
    float* out      = (float*)d_out;

    dim3 grid1(NSPLIT / WPB, GG, BB);   // 8 x 8 x 16 = 1024 blocks
    attn_partial<<<grid1, 256>>>(Q, K, V, csl);

    dim3 grid2(HH, BB);                 // 32 x 16 = 512 blocks
    attn_combine<<<grid2, 128>>>(out);
}